// round 16
// baseline (speedup 1.0000x reference)
#include <cuda_runtime.h>
#include <cstdint>

#define E_DIM 2048
#define H_NUM 32
#define HD 64
#define P_LEN 4096
#define S_LEN 4100
#define M_ROWS 64
#define NPART 8
#define NEG_MAX (-3.4028234663852886e38f)
#define LOG2E 1.4426950408889634f

// ---------------- scratch (device globals: no allocs allowed) ----------------
__device__ __align__(256) float g_q[M_ROWS * E_DIM];      // tf32-rounded, *0.125*log2e
__device__ __align__(256) float g_k[M_ROWS * E_DIM];
__device__ __align__(256) float g_v[M_ROWS * E_DIM];
__device__ __align__(256) float g_attn[M_ROWS * E_DIM];   // tf32-rounded attn output
// opart: [m][h][p][d]  (m*16384 + h*512 + p*64 + d)
__device__ __align__(256) float g_opart[M_ROWS * H_NUM * NPART * HD];
// pm/pl: [m][h][p]  (log2-domain stats)
__device__ __align__(256) float g_pm[M_ROWS * H_NUM * NPART];
__device__ __align__(256) float g_pl[M_ROWS * H_NUM * NPART];
__device__ __align__(256) float g_pp[12 * M_ROWS * E_DIM];   // split-K partials
__device__ int g_cnt[128];                                    // split-K arrival counters (zero-init)

// ---------------- helpers ----------------
__device__ __forceinline__ uint32_t f2tf(float f) {
    uint32_t u;
    asm("cvt.rna.tf32.f32 %0, %1;" : "=r"(u) : "f"(f));
    return u;
}

__device__ __forceinline__ void mma_tf32(float* c, const uint32_t* a, uint32_t b0, uint32_t b1) {
    asm volatile(
        "mma.sync.aligned.m16n8k8.row.col.f32.tf32.tf32.f32 "
        "{%0,%1,%2,%3},{%4,%5,%6,%7},{%8,%9},{%0,%1,%2,%3};"
        : "+f"(c[0]), "+f"(c[1]), "+f"(c[2]), "+f"(c[3])
        : "r"(a[0]), "r"(a[1]), "r"(a[2]), "r"(a[3]), "r"(b0), "r"(b1));
}

__device__ __forceinline__ void cp16(float* smem_dst, const float* gsrc) {
    uint32_t s = (uint32_t)__cvta_generic_to_shared(smem_dst);
    asm volatile("cp.async.cg.shared.global [%0], [%1], 16;" :: "r"(s), "l"(gsrc));
}
__device__ __forceinline__ void cp_commit() {
    asm volatile("cp.async.commit_group;");
}
template<int N> __device__ __forceinline__ void cp_wait() {
    asm volatile("cp.async.wait_group %0;" :: "n"(N));
}

// ---------------- fused W-major split-K projection GEMM + last-block reduction ----------
// C[f, t] = sum_k W[f,k] * A[t,k].  MODE 0: QKV (ksplit 4, mats 3, A=hs).
// MODE 1: O-proj (ksplit 8, 1 mat, A=g_attn pre-rounded tf32, out=dout).
// Each block writes its k-slice partial; the LAST block of each (x,y) tile (atomic
// counter) sums the slots in fixed order (deterministic), adds bias, applies the
// Q scale+tf32-round, writes the final tensor, and resets the counter for replay.
template<int MODE>
__global__ void __launch_bounds__(256) gemm_f(
    const float* __restrict__ A,
    const float* __restrict__ W0, const float* __restrict__ W1, const float* __restrict__ W2,
    const float* __restrict__ b0, const float* __restrict__ b1, const float* __restrict__ b2,
    float* __restrict__ dout)
{
    extern __shared__ float sm[];
    const int STAGE = 128 * 36;
    constexpr int KSPLIT = (MODE == 0) ? 4 : 8;
    constexpr int NMATS  = (MODE == 0) ? 3 : 1;
    constexpr int KSPAN  = E_DIM / KSPLIT;
    constexpr int CNTB   = (MODE == 0) ? 0 : 96;

    if (MODE == 1) A = g_attn;
    const int y = blockIdx.y;
    const float* W    = (y == 0) ? W0 : (y == 1) ? W1 : W2;
    const float* bias = (y == 0) ? b0 : (y == 1) ? b1 : b2;
    const int fbase = blockIdx.x * 64;
    const int k0 = blockIdx.z * KSPAN;
    float* part = g_pp + (size_t)(blockIdx.z * NMATS + y) * (M_ROWS * E_DIM);

    const int tid = threadIdx.x;
    const int lane = tid & 31, wid = tid >> 5;
    const int rb = lane >> 2, cq = lane & 3;
    const int m0 = (wid >> 1) * 16;
    const int n0 = (wid & 1) * 32;

    float c[4][4];
#pragma unroll
    for (int i = 0; i < 4; i++)
#pragma unroll
        for (int j = 0; j < 4; j++) c[i][j] = 0.0f;

    auto load_stage = [&](int buf, int kk0) {
        float* ws = sm + buf * STAGE;
        float* as = ws + 64 * 36;
        int row = tid >> 3, kc = tid & 7;
        cp16(ws + row * 36 + kc * 4,        W + (size_t)(fbase + row) * E_DIM + kk0 + kc * 4);
        cp16(ws + (row + 32) * 36 + kc * 4, W + (size_t)(fbase + row + 32) * E_DIM + kk0 + kc * 4);
        cp16(as + row * 36 + kc * 4,        A + (row) * E_DIM + kk0 + kc * 4);
        cp16(as + (row + 32) * 36 + kc * 4, A + (row + 32) * E_DIM + kk0 + kc * 4);
    };

#pragma unroll
    for (int s = 0; s < 3; s++) { load_stage(s, k0 + s * 32); cp_commit(); }

    const int NITER = KSPAN / 32;
    for (int it = 0; it < NITER; it++) {
        cp_wait<2>();
        __syncthreads();
        float* ws = sm + (it & 3) * STAGE;
        float* as = ws + 64 * 36;
#pragma unroll
        for (int ks = 0; ks < 4; ks++) {
            int kk = ks * 8 + cq;
            uint32_t a[4];
            a[0] = f2tf(ws[(m0 + rb) * 36 + kk]);
            a[1] = f2tf(ws[(m0 + 8 + rb) * 36 + kk]);
            a[2] = f2tf(ws[(m0 + rb) * 36 + kk + 4]);
            a[3] = f2tf(ws[(m0 + 8 + rb) * 36 + kk + 4]);
#pragma unroll
            for (int nf = 0; nf < 4; nf++) {
                int nn = n0 + nf * 8 + rb;
                uint32_t bb0, bb1;
                if (MODE == 1) {
                    bb0 = __float_as_uint(as[nn * 36 + kk]);
                    bb1 = __float_as_uint(as[nn * 36 + kk + 4]);
                } else {
                    bb0 = f2tf(as[nn * 36 + kk]);
                    bb1 = f2tf(as[nn * 36 + kk + 4]);
                }
                mma_tf32(c[nf], a, bb0, bb1);
            }
        }
        int nx = it + 3;
        if (nx < NITER) load_stage(nx & 3, k0 + nx * 32);
        cp_commit();
    }

    const int f = fbase + m0 + rb;
#pragma unroll
    for (int nf = 0; nf < 4; nf++) {
        int t0 = n0 + nf * 8 + cq * 2;
        part[t0 * E_DIM + f]           = c[nf][0];
        part[(t0 + 1) * E_DIM + f]     = c[nf][1];
        part[t0 * E_DIM + f + 8]       = c[nf][2];
        part[(t0 + 1) * E_DIM + f + 8] = c[nf][3];
    }

    // ---- last-block reduction ----
    __threadfence();
    __shared__ int isLast;
    if (tid == 0) {
        int idx = CNTB + y * 32 + blockIdx.x;
        int v = atomicAdd(&g_cnt[idx], 1);
        isLast = (v == KSPLIT - 1);
        if (v == KSPLIT - 1) g_cnt[idx] = 0;   // reset for next replay
    }
    __syncthreads();
    if (!isLast) return;
    __threadfence();

    const float4* pp4 = (const float4*)g_pp;
    float* outp = (MODE == 1) ? dout : (y == 0) ? g_q : (y == 1) ? g_k : g_v;
    const float4* b4 = (const float4*)bias;
    const float QS = 0.125f * LOG2E;
#pragma unroll
    for (int i = 0; i < 4; i++) {
        int g = tid * 4 + i;                 // 0..1023
        int tok = g >> 4, fc = g & 15;
        int idx = tok * 512 + (fbase >> 2) + fc;
        float4 bb = b4[(fbase >> 2) + fc];
        float sx = bb.x, sy = bb.y, sz = bb.z, sw = bb.w;
#pragma unroll
        for (int s = 0; s < KSPLIT; s++) {
            float4 a = pp4[(size_t)(s * NMATS + y) * 32768 + idx];
            sx += a.x; sy += a.y; sz += a.z; sw += a.w;
        }
        if (MODE == 0 && y == 0) {
            sx = __uint_as_float(f2tf(sx * QS));
            sy = __uint_as_float(f2tf(sy * QS));
            sz = __uint_as_float(f2tf(sz * QS));
            sw = __uint_as_float(f2tf(sw * QS));
        }
        ((float4*)outp)[idx] = make_float4(sx, sy, sz, sw);
    }
}

// ---------------- attention: register-resident online-softmax flash decoding (R9) ---------
// Grid 256 = (head h = bid>>3, part p = bid&7). Block = 128 threads = 4 warps.
// Warp w owns rows w*16..+15 x ALL 64 cols of each 64-position chunk; 8 chunks/block.
// log2-domain softmax (Q carries log2e); probs C-frag reused as GEMM-O A-frag.
#define KST 68
#define VST 76
__global__ void __launch_bounds__(128, 2) attn_part(
    const float* __restrict__ kpast, const float* __restrict__ vpast,
    const float* __restrict__ mask)
{
    extern __shared__ float sm[];
    float* ks = sm;                    // 3 x [64][68]
    float* vs = sm + 3 * 64 * KST;     // 3 x [64][76]

    const int tid = threadIdx.x;
    const int lane = tid & 31, wid = tid >> 5;
    const int rb = lane >> 2, cq = lane & 3;
    const int h = blockIdx.x >> 3;
    const int p = blockIdx.x & 7;
    const int r0 = wid * 16 + rb;      // rows r0, r0+8

    uint32_t qa[8][4];
    {
        const float* q0 = g_q + (size_t)r0 * E_DIM + h * HD;
        const float* q1 = q0 + 8 * E_DIM;
#pragma unroll
        for (int kst = 0; kst < 8; kst++) {
            qa[kst][0] = __float_as_uint(q0[kst * 8 + cq]);
            qa[kst][1] = __float_as_uint(q1[kst * 8 + cq]);
            qa[kst][2] = __float_as_uint(q0[kst * 8 + cq + 4]);
            qa[kst][3] = __float_as_uint(q1[kst * 8 + cq + 4]);
        }
    }

    auto prefetch = [&](int ci, int slot) {
        int s0 = (p * 8 + ci) * 64;
        float* kb = ks + slot * (64 * KST);
        float* vb = vs + slot * (64 * VST);
#pragma unroll
        for (int i = 0; i < 8; i++) {
            int cc = tid + i * 128;
            int s = cc >> 4, kc = cc & 15;
            cp16(kb + s * KST + kc * 4, kpast + ((size_t)h * P_LEN + s0 + s) * HD + kc * 4);
        }
#pragma unroll
        for (int i = 0; i < 8; i++) {
            int cc = tid + i * 128;
            int s = cc >> 4, kc = cc & 15;
            cp16(vb + s * VST + kc * 4, vpast + ((size_t)h * P_LEN + s0 + s) * HD + kc * 4);
        }
        cp_commit();
    };

    prefetch(0, 0);
    prefetch(1, 1);

    float M0 = NEG_MAX, M1 = NEG_MAX, L0 = 0.0f, L1 = 0.0f;
    float o[8][4];
#pragma unroll
    for (int i = 0; i < 8; i++)
#pragma unroll
        for (int j = 0; j < 4; j++) o[i][j] = 0.0f;

    for (int ci = 0; ci < 8; ci++) {
        if (ci < 6) cp_wait<1>(); else cp_wait<0>();
        __syncthreads();
        if (ci + 2 < 8) prefetch(ci + 2, (ci + 2) % 3);

        const int slot = ci % 3;
        const float* kb = ks + slot * (64 * KST);
        const float* vb = vs + slot * (64 * VST);
        const int s0 = (p * 8 + ci) * 64;

        float2 mkA[8], mkB[8];
        {
            const float* mrow0 = mask + (size_t)r0 * S_LEN + s0 + 2 * cq;
            const float* mrow1 = mrow0 + 8 * S_LEN;
#pragma unroll
            for (int nf = 0; nf < 8; nf++) {
                mkA[nf] = *(const float2*)(mrow0 + nf * 8);
                mkB[nf] = *(const float2*)(mrow1 + nf * 8);
            }
        }

        float c[8][4];
#pragma unroll
        for (int i = 0; i < 8; i++)
#pragma unroll
            for (int j = 0; j < 4; j++) c[i][j] = 0.0f;
#pragma unroll
        for (int kst = 0; kst < 8; kst++) {
            int kk = kst * 8 + cq;
#pragma unroll
            for (int nf = 0; nf < 8; nf++) {
                const float* kr = kb + (nf * 8 + rb) * KST;
                uint32_t b0 = f2tf(kr[kk]);
                uint32_t b1 = f2tf(kr[kk + 4]);
                mma_tf32(c[nf], qa[kst], b0, b1);
            }
        }

        // mask (scaled into log2 domain) + clamp, then register online softmax (base 2)
        float mx0 = NEG_MAX, mx1 = NEG_MAX;
#pragma unroll
        for (int nf = 0; nf < 8; nf++) {
            c[nf][0] = fmaxf(fmaf(mkA[nf].x, LOG2E, c[nf][0]), NEG_MAX);
            c[nf][1] = fmaxf(fmaf(mkA[nf].y, LOG2E, c[nf][1]), NEG_MAX);
            c[nf][2] = fmaxf(fmaf(mkB[nf].x, LOG2E, c[nf][2]), NEG_MAX);
            c[nf][3] = fmaxf(fmaf(mkB[nf].y, LOG2E, c[nf][3]), NEG_MAX);
            mx0 = fmaxf(mx0, fmaxf(c[nf][0], c[nf][1]));
            mx1 = fmaxf(mx1, fmaxf(c[nf][2], c[nf][3]));
        }
        mx0 = fmaxf(mx0, __shfl_xor_sync(0xffffffffu, mx0, 1));
        mx0 = fmaxf(mx0, __shfl_xor_sync(0xffffffffu, mx0, 2));
        mx1 = fmaxf(mx1, __shfl_xor_sync(0xffffffffu, mx1, 1));
        mx1 = fmaxf(mx1, __shfl_xor_sync(0xffffffffu, mx1, 2));

        float M0n = fmaxf(M0, mx0), M1n = fmaxf(M1, mx1);
        float f0 = exp2f(M0 - M0n), f1 = exp2f(M1 - M1n);

        uint32_t pa[8][4];
        float s0a = 0.0f, s1a = 0.0f;
#pragma unroll
        for (int nf = 0; nf < 8; nf++) {
            float p0 = exp2f(c[nf][0] - M0n); s0a += p0; pa[nf][0] = f2tf(p0);
            float p1 = exp2f(c[nf][1] - M0n); s0a += p1; pa[nf][1] = f2tf(p1);
            float p2 = exp2f(c[nf][2] - M1n); s1a += p2; pa[nf][2] = f2tf(p2);
            float p3 = exp2f(c[nf][3] - M1n); s1a += p3; pa[nf][3] = f2tf(p3);
        }
        s0a += __shfl_xor_sync(0xffffffffu, s0a, 1);
        s0a += __shfl_xor_sync(0xffffffffu, s0a, 2);
        s1a += __shfl_xor_sync(0xffffffffu, s1a, 1);
        s1a += __shfl_xor_sync(0xffffffffu, s1a, 2);
        L0 = L0 * f0 + s0a;  M0 = M0n;
        L1 = L1 * f1 + s1a;  M1 = M1n;

#pragma unroll
        for (int df = 0; df < 8; df++) {
            o[df][0] *= f0; o[df][1] *= f0;
            o[df][2] *= f1; o[df][3] *= f1;
        }
#pragma unroll
        for (int kst = 0; kst < 8; kst++) {
            uint32_t aP[4] = { pa[kst][0], pa[kst][2], pa[kst][1], pa[kst][3] };
            const float* v0 = vb + (kst * 8 + 2 * cq) * VST + rb;
            const float* v1 = v0 + VST;
#pragma unroll
            for (int df = 0; df < 8; df++) {
                uint32_t b0 = f2tf(v0[df * 8]);
                uint32_t b1 = f2tf(v1[df * 8]);
                mma_tf32(o[df], aP, b0, b1);
            }
        }
    }

    {
        float* o0 = g_opart + (size_t)r0 * (H_NUM * NPART * HD) + h * (NPART * HD) + p * HD + 2 * cq;
        float* o1 = o0 + 8 * (H_NUM * NPART * HD);
#pragma unroll
        for (int df = 0; df < 8; df++) {
            *(float2*)(o0 + df * 8) = make_float2(o[df][0], o[df][1]);
            *(float2*)(o1 + df * 8) = make_float2(o[df][2], o[df][3]);
        }
        if (cq == 0) {
            g_pm[r0 * (H_NUM * NPART) + h * NPART + p] = M0;
            g_pl[r0 * (H_NUM * NPART) + h * NPART + p] = L0;
            g_pm[(r0 + 8) * (H_NUM * NPART) + h * NPART + p] = M1;
            g_pl[(r0 + 8) * (H_NUM * NPART) + h * NPART + p] = L1;
        }
    }
}

// ---------------- combine 8 partials/row + the 4 batch-local new KV positions ----------------
// warp per (h,m) row; grid 256 x 8 warps = 2048 rows. log2-domain merge; output tf32-rounded.
__global__ void __launch_bounds__(256) attn_combine(const float* __restrict__ mask)
{
    const int tid = threadIdx.x;
    const int lane = tid & 31;
    const int rg = tid >> 5;
    const int R = blockIdx.x * 8 + rg;
    const int h = R >> 6, m = R & 63, b = m >> 2;

    float2 q2 = *(const float2*)(g_q + m * E_DIM + h * HD + lane * 2);
    float sn[4];
#pragma unroll
    for (int tp = 0; tp < 4; tp++) {
        float2 k2 = *(const float2*)(g_k + (b * 4 + tp) * E_DIM + h * HD + lane * 2);
        float pv = q2.x * k2.x + q2.y * k2.y;
#pragma unroll
        for (int off = 16; off > 0; off >>= 1)
            pv += __shfl_xor_sync(0xffffffffu, pv, off);
        sn[tp] = fmaxf(fmaf(mask[m * S_LEN + P_LEN + tp], LOG2E, pv), NEG_MAX);
    }

    float pmv = g_pm[m * (H_NUM * NPART) + h * NPART + (lane & 7)];
    float plv = g_pl[m * (H_NUM * NPART) + h * NPART + (lane & 7)];

    float M = pmv;
    M = fmaxf(M, __shfl_xor_sync(0xffffffffu, M, 1));
    M = fmaxf(M, __shfl_xor_sync(0xffffffffu, M, 2));
    M = fmaxf(M, __shfl_xor_sync(0xffffffffu, M, 4));
#pragma unroll
    for (int tp = 0; tp < 4; tp++) M = fmaxf(M, sn[tp]);

    float epv = exp2f(pmv - M);
    float L = plv * epv;
    L += __shfl_xor_sync(0xffffffffu, L, 1);
    L += __shfl_xor_sync(0xffffffffu, L, 2);
    L += __shfl_xor_sync(0xffffffffu, L, 4);
    float esn[4];
#pragma unroll
    for (int tp = 0; tp < 4; tp++) { esn[tp] = exp2f(sn[tp] - M); L += esn[tp]; }

    const float* opr = g_opart + (size_t)m * (H_NUM * NPART * HD) + h * (NPART * HD) + lane * 2;
    float ox = 0.0f, oy = 0.0f;
#pragma unroll
    for (int pp = 0; pp < 8; pp++) {
        float w = __shfl_sync(0xffffffffu, epv, pp, 8);
        float2 pt = *(const float2*)(opr + pp * HD);
        ox += pt.x * w; oy += pt.y * w;
    }
#pragma unroll
    for (int tp = 0; tp < 4; tp++) {
        float2 v2 = *(const float2*)(g_v + (b * 4 + tp) * E_DIM + h * HD + lane * 2);
        ox += esn[tp] * v2.x; oy += esn[tp] * v2.y;
    }
    float inv = 1.0f / L;
    float rx = __uint_as_float(f2tf(ox * inv));
    float ry = __uint_as_float(f2tf(oy * inv));
    *(float2*)(g_attn + m * E_DIM + h * HD + lane * 2) = make_float2(rx, ry);
}

// ---------------- launch ----------------
extern "C" void kernel_launch(void* const* d_in, const int* in_sizes, int n_in,
                              void* d_out, int out_size)
{
    const float* hs   = (const float*)d_in[0];
    const float* pk   = (const float*)d_in[1];
    const float* pv   = (const float*)d_in[2];
    const float* mask = (const float*)d_in[3];
    const float* Wq   = (const float*)d_in[4];
    const float* bq   = (const float*)d_in[5];
    const float* Wk   = (const float*)d_in[6];
    const float* bk   = (const float*)d_in[7];
    const float* Wv   = (const float*)d_in[8];
    const float* bv   = (const float*)d_in[9];
    const float* Wo   = (const float*)d_in[10];
    const float* bo   = (const float*)d_in[11];
    float* out = (float*)d_out;

    const int gemm_smem = 4 * 128 * 36 * 4;                  // 73728
    const int attn_smem = 3 * (64 * KST + 64 * VST) * 4;     // 110592

    cudaFuncSetAttribute(gemm_f<0>, cudaFuncAttributeMaxDynamicSharedMemorySize, gemm_smem);
    cudaFuncSetAttribute(gemm_f<1>, cudaFuncAttributeMaxDynamicSharedMemorySize, gemm_smem);
    cudaFuncSetAttribute(attn_part, cudaFuncAttributeMaxDynamicSharedMemorySize, attn_smem);

    // QKV projections + fused split-K reduce (writes g_q [scaled+rounded], g_k, g_v)
    gemm_f<0><<<dim3(32, 3, 4), 256, gemm_smem>>>(hs, Wq, Wk, Wv, bq, bk, bv, nullptr);
    // attention over past cache (register-resident flash decoding, R9 config)
    attn_part<<<256, 128, attn_smem>>>(pk, pv, mask);
    // merge 8 partials + new-token KV (writes tf32-rounded g_attn)
    attn_combine<<<256, 256>>>(mask);
    // output projection + fused split-K reduce -> d_out
    gemm_f<1><<<dim3(32, 1, 8), 256, gemm_smem>>>(nullptr, Wo, nullptr, nullptr, bo, nullptr, nullptr, out);
}

// round 17
// speedup vs baseline: 1.1279x; 1.1279x over previous
#include <cuda_runtime.h>
#include <cstdint>

#define E_DIM 2048
#define H_NUM 32
#define HD 64
#define P_LEN 4096
#define S_LEN 4100
#define M_ROWS 64
#define NPART 8
#define NEG_MAX (-3.4028234663852886e38f)
#define LOG2E 1.4426950408889634f

// ---------------- scratch (device globals: no allocs allowed) ----------------
__device__ __align__(256) float g_q[M_ROWS * E_DIM];      // tf32-rounded, *0.125*log2e
__device__ __align__(256) float g_k[M_ROWS * E_DIM];
__device__ __align__(256) float g_v[M_ROWS * E_DIM];
__device__ __align__(256) float g_attn[M_ROWS * E_DIM];   // tf32-rounded attn output
// opart: [m][h][p][d]  (m*16384 + h*512 + p*64 + d)
__device__ __align__(256) float g_opart[M_ROWS * H_NUM * NPART * HD];
// pm/pl: [m][h][p]  (log2-domain stats)
__device__ __align__(256) float g_pm[M_ROWS * H_NUM * NPART];
__device__ __align__(256) float g_pl[M_ROWS * H_NUM * NPART];
__device__ __align__(256) float g_pp[12 * M_ROWS * E_DIM];   // split-K partials

// ---------------- helpers ----------------
__device__ __forceinline__ uint32_t f2tf(float f) {
    uint32_t u;
    asm("cvt.rna.tf32.f32 %0, %1;" : "=r"(u) : "f"(f));
    return u;
}

__device__ __forceinline__ void mma_tf32(float* c, const uint32_t* a, uint32_t b0, uint32_t b1) {
    asm volatile(
        "mma.sync.aligned.m16n8k8.row.col.f32.tf32.tf32.f32 "
        "{%0,%1,%2,%3},{%4,%5,%6,%7},{%8,%9},{%0,%1,%2,%3};"
        : "+f"(c[0]), "+f"(c[1]), "+f"(c[2]), "+f"(c[3])
        : "r"(a[0]), "r"(a[1]), "r"(a[2]), "r"(a[3]), "r"(b0), "r"(b1));
}

__device__ __forceinline__ void cp16(float* smem_dst, const float* gsrc) {
    uint32_t s = (uint32_t)__cvta_generic_to_shared(smem_dst);
    asm volatile("cp.async.cg.shared.global [%0], [%1], 16;" :: "r"(s), "l"(gsrc));
}
__device__ __forceinline__ void cp_commit() {
    asm volatile("cp.async.commit_group;");
}
template<int N> __device__ __forceinline__ void cp_wait() {
    asm volatile("cp.async.wait_group %0;" :: "n"(N));
}

// ---------------- W-major split-K projection GEMM ----------------
// C[f, t] = sum_k W[f,k] * A[t,k]; grid (32, n_mats, ksplit); A==nullptr -> g_attn.
// partial slot = z*gridDim.y + y.  APRE=1: A already tf32-rounded (skip token-side cvt).
template<int APRE>
__global__ void __launch_bounds__(256) gemm_w(
    const float* __restrict__ A,
    const float* __restrict__ W0, const float* __restrict__ W1, const float* __restrict__ W2,
    int kspan)
{
    extern __shared__ float sm[];
    const int STAGE = 128 * 36;

    if (A == nullptr) A = g_attn;
    const float* W = (blockIdx.y == 0) ? W0 : (blockIdx.y == 1) ? W1 : W2;
    const int fbase = blockIdx.x * 64;
    const int k0 = blockIdx.z * kspan;
    float* part = g_pp + (size_t)(blockIdx.z * gridDim.y + blockIdx.y) * (M_ROWS * E_DIM);

    const int tid = threadIdx.x;
    const int lane = tid & 31, wid = tid >> 5;
    const int rb = lane >> 2, cq = lane & 3;
    const int m0 = (wid >> 1) * 16;
    const int n0 = (wid & 1) * 32;

    float c[4][4];
#pragma unroll
    for (int i = 0; i < 4; i++)
#pragma unroll
        for (int j = 0; j < 4; j++) c[i][j] = 0.0f;

    auto load_stage = [&](int buf, int kk0) {
        float* ws = sm + buf * STAGE;
        float* as = ws + 64 * 36;
        int row = tid >> 3, kc = tid & 7;
        cp16(ws + row * 36 + kc * 4,        W + (size_t)(fbase + row) * E_DIM + kk0 + kc * 4);
        cp16(ws + (row + 32) * 36 + kc * 4, W + (size_t)(fbase + row + 32) * E_DIM + kk0 + kc * 4);
        cp16(as + row * 36 + kc * 4,        A + (row) * E_DIM + kk0 + kc * 4);
        cp16(as + (row + 32) * 36 + kc * 4, A + (row + 32) * E_DIM + kk0 + kc * 4);
    };

#pragma unroll
    for (int s = 0; s < 3; s++) { load_stage(s, k0 + s * 32); cp_commit(); }

    const int NITER = kspan / 32;
    for (int it = 0; it < NITER; it++) {
        cp_wait<2>();
        __syncthreads();
        float* ws = sm + (it & 3) * STAGE;
        float* as = ws + 64 * 36;
#pragma unroll
        for (int ks = 0; ks < 4; ks++) {
            int kk = ks * 8 + cq;
            uint32_t a[4];
            a[0] = f2tf(ws[(m0 + rb) * 36 + kk]);
            a[1] = f2tf(ws[(m0 + 8 + rb) * 36 + kk]);
            a[2] = f2tf(ws[(m0 + rb) * 36 + kk + 4]);
            a[3] = f2tf(ws[(m0 + 8 + rb) * 36 + kk + 4]);
#pragma unroll
            for (int nf = 0; nf < 4; nf++) {
                int nn = n0 + nf * 8 + rb;
                uint32_t b0, b1;
                if (APRE) {
                    b0 = __float_as_uint(as[nn * 36 + kk]);
                    b1 = __float_as_uint(as[nn * 36 + kk + 4]);
                } else {
                    b0 = f2tf(as[nn * 36 + kk]);
                    b1 = f2tf(as[nn * 36 + kk + 4]);
                }
                mma_tf32(c[nf], a, b0, b1);
            }
        }
        int nx = it + 3;
        if (nx < NITER) load_stage(nx & 3, k0 + nx * 32);
        cp_commit();
    }

    const int f = fbase + m0 + rb;
#pragma unroll
    for (int nf = 0; nf < 4; nf++) {
        int t0 = n0 + nf * 8 + cq * 2;
        part[t0 * E_DIM + f]           = c[nf][0];
        part[(t0 + 1) * E_DIM + f]     = c[nf][1];
        part[t0 * E_DIM + f + 8]       = c[nf][2];
        part[(t0 + 1) * E_DIM + f + 8] = c[nf][3];
    }
}

// ---------------- reduce split-K partials ----------------
// QKV: slots {mat, mat+3, mat+6, mat+9}; Q gets scale 0.125*log2e AND tf32 pre-rounding.
__global__ void __launch_bounds__(256) reduce_qkv(
    const float* __restrict__ bq, const float* __restrict__ bk, const float* __restrict__ bv)
{
    int gid = blockIdx.x * 256 + threadIdx.x;    // 0..98303
    int mat = gid >> 15;
    int r = gid & 32767;
    int f4 = r & 511;
    const float4* pp = (const float4*)g_pp;
    float4 a = pp[(size_t)mat * 32768 + r];
    float4 b = pp[(size_t)(mat + 3) * 32768 + r];
    float4 c = pp[(size_t)(mat + 6) * 32768 + r];
    float4 d = pp[(size_t)(mat + 9) * 32768 + r];
    const float* bias = (mat == 0) ? bq : (mat == 1) ? bk : bv;
    float4 bb = ((const float4*)bias)[f4];
    float4 o;
    o.x = a.x + b.x + c.x + d.x + bb.x;
    o.y = a.y + b.y + c.y + d.y + bb.y;
    o.z = a.z + b.z + c.z + d.z + bb.z;
    o.w = a.w + b.w + c.w + d.w + bb.w;
    if (mat == 0) {
        const float QS = 0.125f * LOG2E;
        o.x = __uint_as_float(f2tf(o.x * QS));
        o.y = __uint_as_float(f2tf(o.y * QS));
        o.z = __uint_as_float(f2tf(o.z * QS));
        o.w = __uint_as_float(f2tf(o.w * QS));
    }
    float* out = (mat == 0) ? g_q : (mat == 1) ? g_k : g_v;
    ((float4*)out)[r] = o;
}

// O-proj: slots 0..7, add bias, write d_out. grid 128x256
__global__ void __launch_bounds__(256) reduce_o(const float* __restrict__ bo, float* __restrict__ out)
{
    int r = blockIdx.x * 256 + threadIdx.x;      // 0..32767
    int f4 = r & 511;
    const float4* pp = (const float4*)g_pp;
    float4 bb = ((const float4*)bo)[f4];
    float ox = bb.x, oy = bb.y, oz = bb.z, ow = bb.w;
#pragma unroll
    for (int s = 0; s < 8; s++) {
        float4 a = pp[(size_t)s * 32768 + r];
        ox += a.x; oy += a.y; oz += a.z; ow += a.w;
    }
    ((float4*)out)[r] = make_float4(ox, oy, oz, ow);
}

// ---------------- attention: register-resident online-softmax flash decoding (R9) ---------
// Grid 256 = (head h = bid>>3, part p = bid&7). Block = 128 threads = 4 warps, 2 blocks/SM
// (all 256 blocks resident in one wave). Warp w owns rows w*16..+15 x ALL 64 cols of each
// 64-position chunk; 8 chunks/block. log2-domain softmax (Q carries log2e); KV triple-
// buffered, wait<1>, ONE barrier per chunk; probs C-frag reused as GEMM-O A-frag.
#define KST 68
#define VST 76
__global__ void __launch_bounds__(128, 2) attn_part(
    const float* __restrict__ kpast, const float* __restrict__ vpast,
    const float* __restrict__ mask)
{
    extern __shared__ float sm[];
    float* ks = sm;                    // 3 x [64][68]
    float* vs = sm + 3 * 64 * KST;     // 3 x [64][76]

    const int tid = threadIdx.x;
    const int lane = tid & 31, wid = tid >> 5;
    const int rb = lane >> 2, cq = lane & 3;
    const int h = blockIdx.x >> 3;
    const int p = blockIdx.x & 7;
    const int r0 = wid * 16 + rb;      // rows r0, r0+8

    uint32_t qa[8][4];
    {
        const float* q0 = g_q + (size_t)r0 * E_DIM + h * HD;
        const float* q1 = q0 + 8 * E_DIM;
#pragma unroll
        for (int kst = 0; kst < 8; kst++) {
            qa[kst][0] = __float_as_uint(q0[kst * 8 + cq]);
            qa[kst][1] = __float_as_uint(q1[kst * 8 + cq]);
            qa[kst][2] = __float_as_uint(q0[kst * 8 + cq + 4]);
            qa[kst][3] = __float_as_uint(q1[kst * 8 + cq + 4]);
        }
    }

    auto prefetch = [&](int ci, int slot) {
        int s0 = (p * 8 + ci) * 64;
        float* kb = ks + slot * (64 * KST);
        float* vb = vs + slot * (64 * VST);
#pragma unroll
        for (int i = 0; i < 8; i++) {
            int cc = tid + i * 128;
            int s = cc >> 4, kc = cc & 15;
            cp16(kb + s * KST + kc * 4, kpast + ((size_t)h * P_LEN + s0 + s) * HD + kc * 4);
        }
#pragma unroll
        for (int i = 0; i < 8; i++) {
            int cc = tid + i * 128;
            int s = cc >> 4, kc = cc & 15;
            cp16(vb + s * VST + kc * 4, vpast + ((size_t)h * P_LEN + s0 + s) * HD + kc * 4);
        }
        cp_commit();
    };

    prefetch(0, 0);
    prefetch(1, 1);

    float M0 = NEG_MAX, M1 = NEG_MAX, L0 = 0.0f, L1 = 0.0f;
    float o[8][4];
#pragma unroll
    for (int i = 0; i < 8; i++)
#pragma unroll
        for (int j = 0; j < 4; j++) o[i][j] = 0.0f;

    for (int ci = 0; ci < 8; ci++) {
        if (ci < 6) cp_wait<1>(); else cp_wait<0>();
        __syncthreads();
        if (ci + 2 < 8) prefetch(ci + 2, (ci + 2) % 3);

        const int slot = ci % 3;
        const float* kb = ks + slot * (64 * KST);
        const float* vb = vs + slot * (64 * VST);
        const int s0 = (p * 8 + ci) * 64;

        float2 mkA[8], mkB[8];
        {
            const float* mrow0 = mask + (size_t)r0 * S_LEN + s0 + 2 * cq;
            const float* mrow1 = mrow0 + 8 * S_LEN;
#pragma unroll
            for (int nf = 0; nf < 8; nf++) {
                mkA[nf] = *(const float2*)(mrow0 + nf * 8);
                mkB[nf] = *(const float2*)(mrow1 + nf * 8);
            }
        }

        float c[8][4];
#pragma unroll
        for (int i = 0; i < 8; i++)
#pragma unroll
            for (int j = 0; j < 4; j++) c[i][j] = 0.0f;
#pragma unroll
        for (int kst = 0; kst < 8; kst++) {
            int kk = kst * 8 + cq;
#pragma unroll
            for (int nf = 0; nf < 8; nf++) {
                const float* kr = kb + (nf * 8 + rb) * KST;
                uint32_t b0 = f2tf(kr[kk]);
                uint32_t b1 = f2tf(kr[kk + 4]);
                mma_tf32(c[nf], qa[kst], b0, b1);
            }
        }

        // mask (scaled into log2 domain) + clamp, then register online softmax (base 2)
        float mx0 = NEG_MAX, mx1 = NEG_MAX;
#pragma unroll
        for (int nf = 0; nf < 8; nf++) {
            c[nf][0] = fmaxf(fmaf(mkA[nf].x, LOG2E, c[nf][0]), NEG_MAX);
            c[nf][1] = fmaxf(fmaf(mkA[nf].y, LOG2E, c[nf][1]), NEG_MAX);
            c[nf][2] = fmaxf(fmaf(mkB[nf].x, LOG2E, c[nf][2]), NEG_MAX);
            c[nf][3] = fmaxf(fmaf(mkB[nf].y, LOG2E, c[nf][3]), NEG_MAX);
            mx0 = fmaxf(mx0, fmaxf(c[nf][0], c[nf][1]));
            mx1 = fmaxf(mx1, fmaxf(c[nf][2], c[nf][3]));
        }
        mx0 = fmaxf(mx0, __shfl_xor_sync(0xffffffffu, mx0, 1));
        mx0 = fmaxf(mx0, __shfl_xor_sync(0xffffffffu, mx0, 2));
        mx1 = fmaxf(mx1, __shfl_xor_sync(0xffffffffu, mx1, 1));
        mx1 = fmaxf(mx1, __shfl_xor_sync(0xffffffffu, mx1, 2));

        float M0n = fmaxf(M0, mx0), M1n = fmaxf(M1, mx1);
        float f0 = exp2f(M0 - M0n), f1 = exp2f(M1 - M1n);

        uint32_t pa[8][4];
        float s0a = 0.0f, s1a = 0.0f;
#pragma unroll
        for (int nf = 0; nf < 8; nf++) {
            float p0 = exp2f(c[nf][0] - M0n); s0a += p0; pa[nf][0] = f2tf(p0);
            float p1 = exp2f(c[nf][1] - M0n); s0a += p1; pa[nf][1] = f2tf(p1);
            float p2 = exp2f(c[nf][2] - M1n); s1a += p2; pa[nf][2] = f2tf(p2);
            float p3 = exp2f(c[nf][3] - M1n); s1a += p3; pa[nf][3] = f2tf(p3);
        }
        s0a += __shfl_xor_sync(0xffffffffu, s0a, 1);
        s0a += __shfl_xor_sync(0xffffffffu, s0a, 2);
        s1a += __shfl_xor_sync(0xffffffffu, s1a, 1);
        s1a += __shfl_xor_sync(0xffffffffu, s1a, 2);
        L0 = L0 * f0 + s0a;  M0 = M0n;
        L1 = L1 * f1 + s1a;  M1 = M1n;

#pragma unroll
        for (int df = 0; df < 8; df++) {
            o[df][0] *= f0; o[df][1] *= f0;
            o[df][2] *= f1; o[df][3] *= f1;
        }
#pragma unroll
        for (int kst = 0; kst < 8; kst++) {
            uint32_t aP[4] = { pa[kst][0], pa[kst][2], pa[kst][1], pa[kst][3] };
            const float* v0 = vb + (kst * 8 + 2 * cq) * VST + rb;
            const float* v1 = v0 + VST;
#pragma unroll
            for (int df = 0; df < 8; df++) {
                uint32_t b0 = f2tf(v0[df * 8]);
                uint32_t b1 = f2tf(v1[df * 8]);
                mma_tf32(o[df], aP, b0, b1);
            }
        }
    }

    {
        float* o0 = g_opart + (size_t)r0 * (H_NUM * NPART * HD) + h * (NPART * HD) + p * HD + 2 * cq;
        float* o1 = o0 + 8 * (H_NUM * NPART * HD);
#pragma unroll
        for (int df = 0; df < 8; df++) {
            *(float2*)(o0 + df * 8) = make_float2(o[df][0], o[df][1]);
            *(float2*)(o1 + df * 8) = make_float2(o[df][2], o[df][3]);
        }
        if (cq == 0) {
            g_pm[r0 * (H_NUM * NPART) + h * NPART + p] = M0;
            g_pl[r0 * (H_NUM * NPART) + h * NPART + p] = L0;
            g_pm[(r0 + 8) * (H_NUM * NPART) + h * NPART + p] = M1;
            g_pl[(r0 + 8) * (H_NUM * NPART) + h * NPART + p] = L1;
        }
    }
}

// ---------------- combine 8 partials/row + the 4 batch-local new KV positions ----------------
// warp per (h,m) row; grid 256 x 8 warps = 2048 rows. log2-domain merge; output tf32-rounded.
__global__ void __launch_bounds__(256) attn_combine(const float* __restrict__ mask)
{
    const int tid = threadIdx.x;
    const int lane = tid & 31;
    const int rg = tid >> 5;
    const int R = blockIdx.x * 8 + rg;
    const int h = R >> 6, m = R & 63, b = m >> 2;

    float2 q2 = *(const float2*)(g_q + m * E_DIM + h * HD + lane * 2);
    float sn[4];
#pragma unroll
    for (int tp = 0; tp < 4; tp++) {
        float2 k2 = *(const float2*)(g_k + (b * 4 + tp) * E_DIM + h * HD + lane * 2);
        float pv = q2.x * k2.x + q2.y * k2.y;
#pragma unroll
        for (int off = 16; off > 0; off >>= 1)
            pv += __shfl_xor_sync(0xffffffffu, pv, off);
        sn[tp] = fmaxf(fmaf(mask[m * S_LEN + P_LEN + tp], LOG2E, pv), NEG_MAX);
    }

    float pmv = g_pm[m * (H_NUM * NPART) + h * NPART + (lane & 7)];
    float plv = g_pl[m * (H_NUM * NPART) + h * NPART + (lane & 7)];

    float M = pmv;
    M = fmaxf(M, __shfl_xor_sync(0xffffffffu, M, 1));
    M = fmaxf(M, __shfl_xor_sync(0xffffffffu, M, 2));
    M = fmaxf(M, __shfl_xor_sync(0xffffffffu, M, 4));
#pragma unroll
    for (int tp = 0; tp < 4; tp++) M = fmaxf(M, sn[tp]);

    float epv = exp2f(pmv - M);
    float L = plv * epv;
    L += __shfl_xor_sync(0xffffffffu, L, 1);
    L += __shfl_xor_sync(0xffffffffu, L, 2);
    L += __shfl_xor_sync(0xffffffffu, L, 4);
    float esn[4];
#pragma unroll
    for (int tp = 0; tp < 4; tp++) { esn[tp] = exp2f(sn[tp] - M); L += esn[tp]; }

    const float* opr = g_opart + (size_t)m * (H_NUM * NPART * HD) + h * (NPART * HD) + lane * 2;
    float ox = 0.0f, oy = 0.0f;
#pragma unroll
    for (int pp = 0; pp < 8; pp++) {
        float w = __shfl_sync(0xffffffffu, epv, pp, 8);
        float2 pt = *(const float2*)(opr + pp * HD);
        ox += pt.x * w; oy += pt.y * w;
    }
#pragma unroll
    for (int tp = 0; tp < 4; tp++) {
        float2 v2 = *(const float2*)(g_v + (b * 4 + tp) * E_DIM + h * HD + lane * 2);
        ox += esn[tp] * v2.x; oy += esn[tp] * v2.y;
    }
    float inv = 1.0f / L;
    float rx = __uint_as_float(f2tf(ox * inv));
    float ry = __uint_as_float(f2tf(oy * inv));
    *(float2*)(g_attn + m * E_DIM + h * HD + lane * 2) = make_float2(rx, ry);
}

// ---------------- launch ----------------
extern "C" void kernel_launch(void* const* d_in, const int* in_sizes, int n_in,
                              void* d_out, int out_size)
{
    const float* hs   = (const float*)d_in[0];
    const float* pk   = (const float*)d_in[1];
    const float* pv   = (const float*)d_in[2];
    const float* mask = (const float*)d_in[3];
    const float* Wq   = (const float*)d_in[4];
    const float* bq   = (const float*)d_in[5];
    const float* Wk   = (const float*)d_in[6];
    const float* bk   = (const float*)d_in[7];
    const float* Wv   = (const float*)d_in[8];
    const float* bv   = (const float*)d_in[9];
    const float* Wo   = (const float*)d_in[10];
    const float* bo   = (const float*)d_in[11];
    float* out = (float*)d_out;

    const int gemm_smem = 4 * 128 * 36 * 4;                  // 73728
    const int attn_smem = 3 * (64 * KST + 64 * VST) * 4;     // 110592

    cudaFuncSetAttribute(gemm_w<0>, cudaFuncAttributeMaxDynamicSharedMemorySize, gemm_smem);
    cudaFuncSetAttribute(gemm_w<1>, cudaFuncAttributeMaxDynamicSharedMemorySize, gemm_smem);
    cudaFuncSetAttribute(attn_part, cudaFuncAttributeMaxDynamicSharedMemorySize, attn_smem);

    // QKV projections: split-K 4, 384 blocks
    gemm_w<0><<<dim3(32, 3, 4), 256, gemm_smem>>>(hs, Wq, Wk, Wv, 512);
    reduce_qkv<<<384, 256>>>(bq, bk, bv);
    // attention over past cache (register-resident flash decoding, R9 config, log2 domain)
    attn_part<<<256, 128, attn_smem>>>(pk, pv, mask);
    // merge 8 partials + new-token KV (writes tf32-rounded g_attn)
    attn_combine<<<256, 256>>>(mask);
    // output projection: split-K 8 (A=nullptr -> g_attn device-side, pre-rounded)
    gemm_w<1><<<dim3(32, 1, 8), 256, gemm_smem>>>(nullptr, Wo, nullptr, nullptr, 256);
    reduce_o<<<128, 256>>>(bo, out);
}